// round 1
// baseline (speedup 1.0000x reference)
#include <cuda_runtime.h>
#include <cuda_bf16.h>
#include <math.h>

// ---------------------------------------------------------------------------
// Problem constants
// ---------------------------------------------------------------------------
#define N_SRC1 200000
#define N_TGT1 50000
#define N_TGT2 10000
#define F_IN   256
#define F_HID  192
#define F_OUT  128

// ---------------------------------------------------------------------------
// Scratch (static __device__ arrays; no allocation allowed)
// ---------------------------------------------------------------------------
__device__ float g_agg1[(size_t)N_TGT1 * F_IN];    // 51.2 MB
__device__ float g_cnt1[N_TGT1];
__device__ float g_h1[(size_t)N_TGT1 * F_HID];     // 38.4 MB
__device__ float g_agg2[(size_t)N_TGT2 * F_HID];   // 7.7 MB
__device__ float g_cnt2[N_TGT2];
__device__ float g_h2[(size_t)N_TGT2 * F_HID];
__device__ float g_h3[(size_t)N_TGT2 * F_HID];
__device__ float g_logits[(size_t)N_TGT2 * F_OUT];

// ---------------------------------------------------------------------------
// Edge scatter: warp per edge; atomicAdd feature row into agg[tgt], count++
// ---------------------------------------------------------------------------
__global__ void scatter_kernel(const float* __restrict__ feat,
                               const int* __restrict__ src,
                               const int* __restrict__ tgt,
                               int E, int F,
                               float* __restrict__ agg,
                               float* __restrict__ cnt) {
    int warp = (blockIdx.x * blockDim.x + threadIdx.x) >> 5;
    int lane = threadIdx.x & 31;
    if (warp >= E) return;
    int s = src[warp];
    int t = tgt[warp];
    const float* fr = feat + (size_t)s * F;
    float* ar = agg + (size_t)t * F;
    #pragma unroll 4
    for (int c = lane; c < F; c += 32) {
        atomicAdd(&ar[c], __ldg(&fr[c]));
    }
    if (lane == 0) atomicAdd(&cnt[t], 1.0f);
}

// ---------------------------------------------------------------------------
// Row normalize: agg[r, :] *= 1 / max(cnt[r], 1)
// ---------------------------------------------------------------------------
__global__ void normalize_kernel(float* __restrict__ agg,
                                 const float* __restrict__ cnt,
                                 int M, int F) {
    int idx = blockIdx.x * blockDim.x + threadIdx.x;
    if (idx >= M * F) return;
    int r = idx / F;
    agg[idx] *= 1.0f / fmaxf(cnt[r], 1.0f);
}

// ---------------------------------------------------------------------------
// Tiled SGEMM over a virtual concatenated K dimension:
//   out[m, n] = bias[n] + sum_k A1[m,k] * Wa[n,k]  (k < K1)
//                       + sum_k A2[m,k] * Wb[n,k]  (k < K2)
// BN == N (single block column). Optional linear + relu outputs.
// ---------------------------------------------------------------------------
template <int BM, int BN, int BK, int TM, int TN>
__global__ __launch_bounds__(256, 2)
void gemm_dual(const float* __restrict__ A1, int K1,
               const float* __restrict__ A2, int K2,
               const float* __restrict__ Wa,
               const float* __restrict__ Wb,
               const float* __restrict__ bias,
               int M,
               float* __restrict__ outLin,
               float* __restrict__ outRelu) {
    static_assert((BM / TM) * (BN / TN) == 256, "thread count");
    __shared__ float As[BK][BM];
    __shared__ float Bs[BK][BN + 4];

    const int tid = threadIdx.x;
    const int tx = tid % (BN / TN);
    const int ty = tid / (BN / TN);
    const int rowBase = blockIdx.x * BM;

    float acc[TM][TN];
    #pragma unroll
    for (int i = 0; i < TM; i++)
        #pragma unroll
        for (int j = 0; j < TN; j++) acc[i][j] = 0.0f;

    const int Ktot = K1 + K2;
    for (int k0 = 0; k0 < Ktot; k0 += BK) {
        const float* A;
        const float* W;
        int K, kk0;
        if (k0 < K1) { A = A1; W = Wa; K = K1; kk0 = k0; }
        else         { A = A2; W = Wb; K = K2; kk0 = k0 - K1; }

        // Load A tile (BM x BK), float4 along K, store transposed.
        #pragma unroll
        for (int i = 0; i < (BM * BK) / (4 * 256); i++) {
            int f = tid + i * 256;
            int m = f / (BK / 4);
            int kq = f % (BK / 4);
            int gr = rowBase + m;
            float4 v = make_float4(0.f, 0.f, 0.f, 0.f);
            if (gr < M)
                v = *reinterpret_cast<const float4*>(&A[(size_t)gr * K + kk0 + kq * 4]);
            As[kq * 4 + 0][m] = v.x;
            As[kq * 4 + 1][m] = v.y;
            As[kq * 4 + 2][m] = v.z;
            As[kq * 4 + 3][m] = v.w;
        }
        // Load W tile (BN x BK), store transposed into Bs[k][n].
        #pragma unroll
        for (int i = 0; i < (BN * BK) / (4 * 256); i++) {
            int f = tid + i * 256;
            int j = f / (BK / 4);
            int kq = f % (BK / 4);
            float4 v = *reinterpret_cast<const float4*>(&W[(size_t)j * K + kk0 + kq * 4]);
            Bs[kq * 4 + 0][j] = v.x;
            Bs[kq * 4 + 1][j] = v.y;
            Bs[kq * 4 + 2][j] = v.z;
            Bs[kq * 4 + 3][j] = v.w;
        }
        __syncthreads();

        #pragma unroll
        for (int kk = 0; kk < BK; kk++) {
            float a[TM], b[TN];
            #pragma unroll
            for (int i = 0; i < TM; i += 4)
                *reinterpret_cast<float4*>(&a[i]) =
                    *reinterpret_cast<const float4*>(&As[kk][ty * TM + i]);
            #pragma unroll
            for (int j = 0; j < TN; j += 4)
                *reinterpret_cast<float4*>(&b[j]) =
                    *reinterpret_cast<const float4*>(&Bs[kk][tx * TN + j]);
            #pragma unroll
            for (int i = 0; i < TM; i++)
                #pragma unroll
                for (int j = 0; j < TN; j++)
                    acc[i][j] = fmaf(a[i], b[j], acc[i][j]);
        }
        __syncthreads();
    }

    // Epilogue
    #pragma unroll
    for (int i = 0; i < TM; i++) {
        int gr = rowBase + ty * TM + i;
        if (gr >= M) continue;
        #pragma unroll
        for (int j = 0; j < TN; j++) {
            int gc = tx * TN + j;
            float v = acc[i][j] + __ldg(&bias[gc]);
            size_t o = (size_t)gr * BN + gc;
            if (outLin)  outLin[o] = v;
            if (outRelu) outRelu[o] = fmaxf(v, 0.0f);
        }
    }
}

// ---------------------------------------------------------------------------
// log_softmax over rows of 128: one warp per row
// ---------------------------------------------------------------------------
__global__ void logsoftmax_kernel(const float* __restrict__ logits,
                                  float* __restrict__ out, int M) {
    int warp = (blockIdx.x * blockDim.x + threadIdx.x) >> 5;
    int lane = threadIdx.x & 31;
    if (warp >= M) return;
    float4 v = reinterpret_cast<const float4*>(logits + (size_t)warp * 128)[lane];
    float m = fmaxf(fmaxf(v.x, v.y), fmaxf(v.z, v.w));
    #pragma unroll
    for (int o = 16; o; o >>= 1) m = fmaxf(m, __shfl_xor_sync(0xFFFFFFFFu, m, o));
    float s = expf(v.x - m) + expf(v.y - m) + expf(v.z - m) + expf(v.w - m);
    #pragma unroll
    for (int o = 16; o; o >>= 1) s += __shfl_xor_sync(0xFFFFFFFFu, s, o);
    float lse = m + logf(s);
    float4 r = make_float4(v.x - lse, v.y - lse, v.z - lse, v.w - lse);
    reinterpret_cast<float4*>(out + (size_t)warp * 128)[lane] = r;
}

// ---------------------------------------------------------------------------
// Launch
// ---------------------------------------------------------------------------
extern "C" void kernel_launch(void* const* d_in, const int* in_sizes, int n_in,
                              void* d_out, int out_size) {
    const float* x   = (const float*)d_in[0];
    const int*   ei1 = (const int*)d_in[1];
    const int*   ei2 = (const int*)d_in[2];
    const float* Wl1 = (const float*)d_in[3];
    const float* bl1 = (const float*)d_in[4];
    const float* Wr1 = (const float*)d_in[5];
    const float* Wl2 = (const float*)d_in[6];
    const float* bl2 = (const float*)d_in[7];
    const float* Wr2 = (const float*)d_in[8];
    const float* W1  = (const float*)d_in[9];
    const float* b1  = (const float*)d_in[10];
    const float* W2  = (const float*)d_in[11];
    const float* b2  = (const float*)d_in[12];

    const int E1 = in_sizes[1] / 2;
    const int E2 = in_sizes[2] / 2;

    float* out_ls  = (float*)d_out;                          // [10000, 128]
    float* out_emb = (float*)d_out + (size_t)N_TGT2 * F_OUT; // [10000, 192]

    float *agg1, *cnt1, *h1, *agg2, *cnt2, *h2, *h3, *logits;
    cudaGetSymbolAddress((void**)&agg1, g_agg1);
    cudaGetSymbolAddress((void**)&cnt1, g_cnt1);
    cudaGetSymbolAddress((void**)&h1, g_h1);
    cudaGetSymbolAddress((void**)&agg2, g_agg2);
    cudaGetSymbolAddress((void**)&cnt2, g_cnt2);
    cudaGetSymbolAddress((void**)&h2, g_h2);
    cudaGetSymbolAddress((void**)&h3, g_h3);
    cudaGetSymbolAddress((void**)&logits, g_logits);

    // ---- Layer 1: aggregate + SAGE conv ----
    cudaMemsetAsync(agg1, 0, (size_t)N_TGT1 * F_IN * sizeof(float));
    cudaMemsetAsync(cnt1, 0, (size_t)N_TGT1 * sizeof(float));
    {
        int warpsPerBlock = 8;  // 256 threads
        int blocks = (E1 + warpsPerBlock - 1) / warpsPerBlock;
        scatter_kernel<<<blocks, 256>>>(x, ei1, ei1 + E1, E1, F_IN, agg1, cnt1);
    }
    {
        int total = N_TGT1 * F_IN;
        normalize_kernel<<<(total + 255) / 256, 256>>>(agg1, cnt1, N_TGT1, F_IN);
    }
    {
        int blocks = (N_TGT1 + 127) / 128;
        gemm_dual<128, 192, 16, 8, 12><<<blocks, 256>>>(
            agg1, F_IN, x, F_IN, Wl1, Wr1, bl1, N_TGT1, nullptr, h1);
    }

    // ---- Layer 2: aggregate + SAGE conv ----
    cudaMemsetAsync(agg2, 0, (size_t)N_TGT2 * F_HID * sizeof(float));
    cudaMemsetAsync(cnt2, 0, (size_t)N_TGT2 * sizeof(float));
    {
        int warpsPerBlock = 8;
        int blocks = (E2 + warpsPerBlock - 1) / warpsPerBlock;
        scatter_kernel<<<blocks, 256>>>(h1, ei2, ei2 + E2, E2, F_HID, agg2, cnt2);
    }
    {
        int total = N_TGT2 * F_HID;
        normalize_kernel<<<(total + 255) / 256, 256>>>(agg2, cnt2, N_TGT2, F_HID);
    }
    {
        int blocks = (N_TGT2 + 127) / 128;
        gemm_dual<128, 192, 16, 8, 12><<<blocks, 256>>>(
            agg2, F_HID, h1, F_HID, Wl2, Wr2, bl2, N_TGT2, nullptr, h2);
    }

    // ---- MLP head ----
    {
        int blocks = (N_TGT2 + 127) / 128;
        // embedding = h2 @ W1^T + b1 ; h3 = relu(embedding)
        gemm_dual<128, 192, 16, 8, 12><<<blocks, 256>>>(
            h2, F_HID, nullptr, 0, W1, nullptr, b1, N_TGT2, out_emb, h3);
        // logits = h3 @ W2^T + b2
        gemm_dual<128, 128, 16, 8, 8><<<blocks, 256>>>(
            h3, F_HID, nullptr, 0, W2, nullptr, b2, N_TGT2, logits, nullptr);
    }

    // ---- log_softmax ----
    {
        int warpsPerBlock = 8;
        int blocks = (N_TGT2 + warpsPerBlock - 1) / warpsPerBlock;
        logsoftmax_kernel<<<blocks, 256>>>(logits, out_ls, N_TGT2);
    }
}

// round 2
// speedup vs baseline: 1.4907x; 1.4907x over previous
#include <cuda_runtime.h>
#include <cuda_bf16.h>
#include <math.h>
#include <stdint.h>

// ---------------------------------------------------------------------------
// Problem constants
// ---------------------------------------------------------------------------
#define N_SRC1 200000
#define N_TGT1 50000
#define N_TGT2 10000
#define F_IN   256
#define F_HID  192
#define F_OUT  128
#define E1_MAX 1000000
#define E2_MAX 300000

// ---------------------------------------------------------------------------
// Scratch (static __device__ arrays; no allocation allowed)
// ---------------------------------------------------------------------------
__device__ float g_agg1[(size_t)N_TGT1 * F_IN];    // 51.2 MB
__device__ float g_h1[(size_t)N_TGT1 * F_HID];     // 38.4 MB
__device__ float g_agg2[(size_t)N_TGT2 * F_HID];
__device__ float g_h2[(size_t)N_TGT2 * F_HID];
__device__ float g_h3[(size_t)N_TGT2 * F_HID];
__device__ float g_logits[(size_t)N_TGT2 * F_OUT];

__device__ int g_icnt1[N_TGT1];
__device__ int g_rowptr1[N_TGT1 + 1];
__device__ int g_cursor1[N_TGT1];
__device__ int g_sorted1[E1_MAX];
__device__ int g_icnt2[N_TGT2];
__device__ int g_rowptr2[N_TGT2 + 1];
__device__ int g_cursor2[N_TGT2];
__device__ int g_sorted2[E2_MAX];

// ---------------------------------------------------------------------------
// PTX helpers
// ---------------------------------------------------------------------------
__device__ __forceinline__ uint32_t smem_u32(const void* p) {
    uint32_t a;
    asm("{ .reg .u64 t; cvta.to.shared.u64 t, %1; cvt.u32.u64 %0, t; }"
        : "=r"(a) : "l"(p));
    return a;
}

#define LDSM4(r0, r1, r2, r3, addr)                                            \
    asm volatile("ldmatrix.sync.aligned.m8n8.x4.shared.b16 {%0,%1,%2,%3},[%4];"\
                 : "=r"(r0), "=r"(r1), "=r"(r2), "=r"(r3) : "r"(addr))

#define LDSM2(r0, r1, addr)                                                    \
    asm volatile("ldmatrix.sync.aligned.m8n8.x2.shared.b16 {%0,%1},[%2];"      \
                 : "=r"(r0), "=r"(r1) : "r"(addr))

__device__ __forceinline__ void mma8(float4& d, const uint32_t* a,
                                     uint32_t b0, uint32_t b1) {
    asm volatile(
        "mma.sync.aligned.m16n8k8.row.col.f32.tf32.tf32.f32 "
        "{%0,%1,%2,%3},{%4,%5,%6,%7},{%8,%9},{%0,%1,%2,%3};"
        : "+f"(d.x), "+f"(d.y), "+f"(d.z), "+f"(d.w)
        : "r"(a[0]), "r"(a[1]), "r"(a[2]), "r"(a[3]), "r"(b0), "r"(b1));
}

// exact split: f == hi + lo, hi is tf32-representable (truncate low 13 bits)
__device__ __forceinline__ void split32(uint32_t v, uint32_t& hi, uint32_t& lo) {
    uint32_t h = v & 0xFFFFE000u;
    float f  = __uint_as_float(v);
    float fh = __uint_as_float(h);
    hi = h;
    lo = __float_as_uint(f - fh);
}

// ---------------------------------------------------------------------------
// CSR build: histogram, scan, fill
// ---------------------------------------------------------------------------
__global__ void hist_kernel(const int* __restrict__ tgt, int E,
                            int* __restrict__ cnt) {
    int i = blockIdx.x * blockDim.x + threadIdx.x;
    if (i < E) atomicAdd(&cnt[tgt[i]], 1);
}

__global__ void scan_kernel(const int* __restrict__ cnt, int n,
                            int* __restrict__ rowptr, int* __restrict__ cursor) {
    __shared__ int wsum[32];
    __shared__ int carry_s;
    int tid = threadIdx.x;
    int lane = tid & 31;
    int wid = tid >> 5;
    if (tid == 0) carry_s = 0;
    __syncthreads();
    for (int base = 0; base < n; base += 1024) {
        int v = (base + tid < n) ? cnt[base + tid] : 0;
        int incl = v;
        #pragma unroll
        for (int off = 1; off < 32; off <<= 1) {
            int t = __shfl_up_sync(0xFFFFFFFFu, incl, off);
            if (lane >= off) incl += t;
        }
        if (lane == 31) wsum[wid] = incl;
        __syncthreads();
        if (wid == 0) {
            int wv = wsum[lane];
            int wi = wv;
            #pragma unroll
            for (int off = 1; off < 32; off <<= 1) {
                int t = __shfl_up_sync(0xFFFFFFFFu, wi, off);
                if (lane >= off) wi += t;
            }
            wsum[lane] = wi;  // inclusive scan of warp sums
        }
        __syncthreads();
        int woff = (wid > 0 ? wsum[wid - 1] : 0) + carry_s;
        int excl = incl - v + woff;
        if (base + tid < n) {
            rowptr[base + tid] = excl;
            cursor[base + tid] = excl;
        }
        __syncthreads();
        if (tid == 0) carry_s += wsum[31];
        __syncthreads();
    }
    if (threadIdx.x == 0) rowptr[n] = carry_s;
}

__global__ void fill_kernel(const int* __restrict__ src,
                            const int* __restrict__ tgt, int E,
                            int* __restrict__ cursor, int* __restrict__ sorted) {
    int i = blockIdx.x * blockDim.x + threadIdx.x;
    if (i < E) {
        int p = atomicAdd(&cursor[tgt[i]], 1);
        sorted[p] = src[i];
    }
}

// ---------------------------------------------------------------------------
// Gather-aggregate (mean): one 64-thread block per target row, float4 lanes
// ---------------------------------------------------------------------------
template <int F4>
__global__ __launch_bounds__(64)
void aggregate_kernel(const float4* __restrict__ x4,
                      const int* __restrict__ rowptr,
                      const int* __restrict__ srcs,
                      float4* __restrict__ out4) {
    int t = blockIdx.x;
    int tid = threadIdx.x;
    int beg = rowptr[t];
    int end = rowptr[t + 1];
    if (tid >= F4) return;

    float4 a0 = {0.f, 0.f, 0.f, 0.f}, a1 = a0, a2 = a0, a3 = a0;
    int e = beg;
    for (; e + 4 <= end; e += 4) {
        int s0 = __ldg(&srcs[e + 0]);
        int s1 = __ldg(&srcs[e + 1]);
        int s2 = __ldg(&srcs[e + 2]);
        int s3 = __ldg(&srcs[e + 3]);
        float4 v0 = __ldg(&x4[(size_t)s0 * F4 + tid]);
        float4 v1 = __ldg(&x4[(size_t)s1 * F4 + tid]);
        float4 v2 = __ldg(&x4[(size_t)s2 * F4 + tid]);
        float4 v3 = __ldg(&x4[(size_t)s3 * F4 + tid]);
        a0.x += v0.x; a0.y += v0.y; a0.z += v0.z; a0.w += v0.w;
        a1.x += v1.x; a1.y += v1.y; a1.z += v1.z; a1.w += v1.w;
        a2.x += v2.x; a2.y += v2.y; a2.z += v2.z; a2.w += v2.w;
        a3.x += v3.x; a3.y += v3.y; a3.z += v3.z; a3.w += v3.w;
    }
    for (; e < end; e++) {
        int s = __ldg(&srcs[e]);
        float4 v = __ldg(&x4[(size_t)s * F4 + tid]);
        a0.x += v.x; a0.y += v.y; a0.z += v.z; a0.w += v.w;
    }
    float inv = 1.0f / fmaxf((float)(end - beg), 1.0f);
    float4 r;
    r.x = (a0.x + a1.x + a2.x + a3.x) * inv;
    r.y = (a0.y + a1.y + a2.y + a3.y) * inv;
    r.z = (a0.z + a1.z + a2.z + a3.z) * inv;
    r.w = (a0.w + a1.w + a2.w + a3.w) * inv;
    out4[(size_t)t * F4 + tid] = r;
}

// ---------------------------------------------------------------------------
// Tensor-core tf32 GEMM (3-pass hi/lo split for fp32-class accuracy).
//   out[m,n] = bias[n] + A1[m,:K1] @ Wa[n,:K1]^T  (+ A2[m,:K2] @ Wb[n,:K2]^T)
// BM=64, BN == N (192 or 128), BK=32, 512 threads (16 warps, warp tile 32xWN).
// ---------------------------------------------------------------------------
template <int BN>
__global__ __launch_bounds__(512, 1)
void gemm_mma(const float* __restrict__ A1, int K1,
              const float* __restrict__ A2, int K2,
              const float* __restrict__ Wa, const float* __restrict__ Wb,
              const float* __restrict__ bias, int M,
              float* __restrict__ outLin, float* __restrict__ outRelu) {
    constexpr int BM = 64, BK = 32, LDP = BK + 4;  // padded row: conflict-free ldmatrix
    constexpr int WN = BN / 8;   // 24 or 16 cols per warp
    constexpr int NF = WN / 8;   // 3 or 2 n-fragments

    __shared__ float As[BM][LDP];
    __shared__ float Bs[BN][LDP];

    const int tid  = threadIdx.x;
    const int lane = tid & 31;
    const int w    = tid >> 5;
    const int wm   = w >> 3;   // 0..1  -> 32 rows each
    const int wn   = w & 7;    // 0..7  -> WN cols each
    const int rowBase = blockIdx.x * BM;

    // ldmatrix per-lane source offsets (float units)
    const int tA = lane >> 3;
    const int rA = ((tA & 1) << 3) | (lane & 7);
    const int cA = (tA >> 1) << 2;
    int aoff[2];
    #pragma unroll
    for (int ms = 0; ms < 2; ms++)
        aoff[ms] = (wm * 32 + ms * 16 + rA) * LDP + cA;

    const int gB = lane >> 3;
    const int rB = lane & 7;
    const int boffA = (wn * WN + ((gB & 2) ? 8 : 0) + rB) * LDP + ((gB & 1) << 2);
    const int boffB = (wn * WN + 16 + rB) * LDP + ((gB & 1) << 2);  // used if NF==3

    const uint32_t asBase = smem_u32(&As[0][0]);
    const uint32_t bsBase = smem_u32(&Bs[0][0]);

    float4 C[2][NF];
    #pragma unroll
    for (int i = 0; i < 2; i++)
        #pragma unroll
        for (int j = 0; j < NF; j++) C[i][j] = make_float4(0.f, 0.f, 0.f, 0.f);

    const int Ktot = K1 + (A2 ? K2 : 0);
    for (int k0 = 0; k0 < Ktot; k0 += BK) {
        const float* A;
        const float* W;
        int K, kk0;
        if (k0 < K1) { A = A1; W = Wa; K = K1; kk0 = k0; }
        else         { A = A2; W = Wb; K = K2; kk0 = k0 - K1; }

        // load A tile: 64x32 = 512 float4, one per thread
        {
            int m = tid >> 3, kq = tid & 7;
            int gr = rowBase + m;
            float4 v = make_float4(0.f, 0.f, 0.f, 0.f);
            if (gr < M)
                v = *reinterpret_cast<const float4*>(&A[(size_t)gr * K + kk0 + (kq << 2)]);
            *reinterpret_cast<float4*>(&As[m][kq << 2]) = v;
        }
        // load B tile: BN x 32
        #pragma unroll
        for (int it = 0; it < (BN * 8) / 512; it++) {
            int f = tid + it * 512;
            int n = f >> 3, kq = f & 7;
            *reinterpret_cast<float4*>(&Bs[n][kq << 2]) =
                *reinterpret_cast<const float4*>(&W[(size_t)n * K + kk0 + (kq << 2)]);
        }
        __syncthreads();

        #pragma unroll
        for (int kk = 0; kk < BK; kk += 8) {
            uint32_t ahi[2][4], alo[2][4];
            #pragma unroll
            for (int ms = 0; ms < 2; ms++) {
                uint32_t r0, r1, r2, r3;
                LDSM4(r0, r1, r2, r3, asBase + (uint32_t)((aoff[ms] + kk) * 4));
                split32(r0, ahi[ms][0], alo[ms][0]);
                split32(r1, ahi[ms][1], alo[ms][1]);
                split32(r2, ahi[ms][2], alo[ms][2]);
                split32(r3, ahi[ms][3], alo[ms][3]);
            }
            uint32_t bhi[NF][2], blo[NF][2];
            {
                uint32_t r0, r1, r2, r3;
                LDSM4(r0, r1, r2, r3, bsBase + (uint32_t)((boffA + kk) * 4));
                split32(r0, bhi[0][0], blo[0][0]);
                split32(r1, bhi[0][1], blo[0][1]);
                split32(r2, bhi[1][0], blo[1][0]);
                split32(r3, bhi[1][1], blo[1][1]);
            }
            if (NF == 3) {
                uint32_t r0, r1;
                LDSM2(r0, r1, bsBase + (uint32_t)((boffB + kk) * 4));
                split32(r0, bhi[NF - 1][0], blo[NF - 1][0]);
                split32(r1, bhi[NF - 1][1], blo[NF - 1][1]);
            }
            #pragma unroll
            for (int ms = 0; ms < 2; ms++)
                #pragma unroll
                for (int nf = 0; nf < NF; nf++) {
                    mma8(C[ms][nf], ahi[ms], bhi[nf][0], bhi[nf][1]);
                    mma8(C[ms][nf], alo[ms], bhi[nf][0], bhi[nf][1]);
                    mma8(C[ms][nf], ahi[ms], blo[nf][0], blo[nf][1]);
                }
        }
        __syncthreads();
    }

    // epilogue: c0,c1 -> (row g, cols q*2, q*2+1); c2,c3 -> row g+8
    const int g = lane >> 2, q = lane & 3;
    #pragma unroll
    for (int ms = 0; ms < 2; ms++) {
        int r0 = rowBase + wm * 32 + ms * 16 + g;
        #pragma unroll
        for (int nf = 0; nf < NF; nf++) {
            int col = wn * WN + nf * 8 + q * 2;
            float b0 = __ldg(&bias[col]);
            float b1 = __ldg(&bias[col + 1]);
            float4 c = C[ms][nf];
            if (r0 < M) {
                size_t o = (size_t)r0 * BN + col;
                if (outLin)  { outLin[o] = c.x + b0;  outLin[o + 1] = c.y + b1; }
                if (outRelu) { outRelu[o] = fmaxf(c.x + b0, 0.f);
                               outRelu[o + 1] = fmaxf(c.y + b1, 0.f); }
            }
            if (r0 + 8 < M) {
                size_t o = (size_t)(r0 + 8) * BN + col;
                if (outLin)  { outLin[o] = c.z + b0;  outLin[o + 1] = c.w + b1; }
                if (outRelu) { outRelu[o] = fmaxf(c.z + b0, 0.f);
                               outRelu[o + 1] = fmaxf(c.w + b1, 0.f); }
            }
        }
    }
}

// ---------------------------------------------------------------------------
// log_softmax over rows of 128: one warp per row
// ---------------------------------------------------------------------------
__global__ void logsoftmax_kernel(const float* __restrict__ logits,
                                  float* __restrict__ out, int M) {
    int warp = (blockIdx.x * blockDim.x + threadIdx.x) >> 5;
    int lane = threadIdx.x & 31;
    if (warp >= M) return;
    float4 v = reinterpret_cast<const float4*>(logits + (size_t)warp * 128)[lane];
    float m = fmaxf(fmaxf(v.x, v.y), fmaxf(v.z, v.w));
    #pragma unroll
    for (int o = 16; o; o >>= 1) m = fmaxf(m, __shfl_xor_sync(0xFFFFFFFFu, m, o));
    float s = expf(v.x - m) + expf(v.y - m) + expf(v.z - m) + expf(v.w - m);
    #pragma unroll
    for (int o = 16; o; o >>= 1) s += __shfl_xor_sync(0xFFFFFFFFu, s, o);
    float lse = m + logf(s);
    float4 r = make_float4(v.x - lse, v.y - lse, v.z - lse, v.w - lse);
    reinterpret_cast<float4*>(out + (size_t)warp * 128)[lane] = r;
}

// ---------------------------------------------------------------------------
// Launch
// ---------------------------------------------------------------------------
extern "C" void kernel_launch(void* const* d_in, const int* in_sizes, int n_in,
                              void* d_out, int out_size) {
    const float* x   = (const float*)d_in[0];
    const int*   ei1 = (const int*)d_in[1];
    const int*   ei2 = (const int*)d_in[2];
    const float* Wl1 = (const float*)d_in[3];
    const float* bl1 = (const float*)d_in[4];
    const float* Wr1 = (const float*)d_in[5];
    const float* Wl2 = (const float*)d_in[6];
    const float* bl2 = (const float*)d_in[7];
    const float* Wr2 = (const float*)d_in[8];
    const float* W1  = (const float*)d_in[9];
    const float* b1  = (const float*)d_in[10];
    const float* W2  = (const float*)d_in[11];
    const float* b2  = (const float*)d_in[12];

    const int E1 = in_sizes[1] / 2;
    const int E2 = in_sizes[2] / 2;

    float* out_ls  = (float*)d_out;                          // [10000, 128]
    float* out_emb = (float*)d_out + (size_t)N_TGT2 * F_OUT; // [10000, 192]

    float *agg1, *h1, *agg2, *h2, *h3, *logits;
    int *icnt1, *rowptr1, *cursor1, *sorted1;
    int *icnt2, *rowptr2, *cursor2, *sorted2;
    cudaGetSymbolAddress((void**)&agg1, g_agg1);
    cudaGetSymbolAddress((void**)&h1, g_h1);
    cudaGetSymbolAddress((void**)&agg2, g_agg2);
    cudaGetSymbolAddress((void**)&h2, g_h2);
    cudaGetSymbolAddress((void**)&h3, g_h3);
    cudaGetSymbolAddress((void**)&logits, g_logits);
    cudaGetSymbolAddress((void**)&icnt1, g_icnt1);
    cudaGetSymbolAddress((void**)&rowptr1, g_rowptr1);
    cudaGetSymbolAddress((void**)&cursor1, g_cursor1);
    cudaGetSymbolAddress((void**)&sorted1, g_sorted1);
    cudaGetSymbolAddress((void**)&icnt2, g_icnt2);
    cudaGetSymbolAddress((void**)&rowptr2, g_rowptr2);
    cudaGetSymbolAddress((void**)&cursor2, g_cursor2);
    cudaGetSymbolAddress((void**)&sorted2, g_sorted2);

    // ---- Layer 1: CSR build + gather-aggregate (mean) ----
    cudaMemsetAsync(icnt1, 0, N_TGT1 * sizeof(int));
    hist_kernel<<<(E1 + 255) / 256, 256>>>(ei1 + E1, E1, icnt1);
    scan_kernel<<<1, 1024>>>(icnt1, N_TGT1, rowptr1, cursor1);
    fill_kernel<<<(E1 + 255) / 256, 256>>>(ei1, ei1 + E1, E1, cursor1, sorted1);
    aggregate_kernel<F_IN / 4><<<N_TGT1, 64>>>(
        (const float4*)x, rowptr1, sorted1, (float4*)agg1);
    gemm_mma<192><<<(N_TGT1 + 63) / 64, 512>>>(
        agg1, F_IN, x, F_IN, Wl1, Wr1, bl1, N_TGT1, nullptr, h1);

    // ---- Layer 2 ----
    cudaMemsetAsync(icnt2, 0, N_TGT2 * sizeof(int));
    hist_kernel<<<(E2 + 255) / 256, 256>>>(ei2 + E2, E2, icnt2);
    scan_kernel<<<1, 1024>>>(icnt2, N_TGT2, rowptr2, cursor2);
    fill_kernel<<<(E2 + 255) / 256, 256>>>(ei2, ei2 + E2, E2, cursor2, sorted2);
    aggregate_kernel<F_HID / 4><<<N_TGT2, 64>>>(
        (const float4*)h1, rowptr2, sorted2, (float4*)agg2);
    gemm_mma<192><<<(N_TGT2 + 63) / 64, 512>>>(
        agg2, F_HID, h1, F_HID, Wl2, Wr2, bl2, N_TGT2, nullptr, h2);

    // ---- MLP head ----
    gemm_mma<192><<<(N_TGT2 + 63) / 64, 512>>>(
        h2, F_HID, nullptr, 0, W1, nullptr, b1, N_TGT2, out_emb, h3);
    gemm_mma<128><<<(N_TGT2 + 63) / 64, 512>>>(
        h3, F_HID, nullptr, 0, W2, nullptr, b2, N_TGT2, logits, nullptr);

    // ---- log_softmax ----
    logsoftmax_kernel<<<(N_TGT2 + 7) / 8, 256>>>(logits, out_ls, N_TGT2);
}